// round 1
// baseline (speedup 1.0000x reference)
#include <cuda_runtime.h>
#include <math.h>
#include <stdint.h>

#define N_OBJ   128
#define HW      36864      // 192*192
#define CLSD    128
#define POSD    64
#define TP      128        // pixels per block
#define KC      32         // m-chunk

// Scratch (allocation-free rule: __device__ globals)
__device__ float g_S[N_OBJ * N_OBJ];      // raw sigmoid overlap scores, [i][j]
__device__ float g_relT[N_OBJ * N_OBJ];   // relation_score transposed: relT[m][n]

__device__ __forceinline__ float fsigmoid(float x) {
    return __fdividef(1.0f, 1.0f + __expf(-x));
}

// ---------------------------------------------------------------------------
// Kernel A: S[i][j] = sigmoid( cls_term(i,j) + pos_term(i,j) )
// grid: 128 blocks (i), 128 threads (j)
// ---------------------------------------------------------------------------
__global__ void score_kernel(const float* __restrict__ bbox,
                             const float* __restrict__ W_U,
                             const float* __restrict__ W_V,
                             const float* __restrict__ W_pos,
                             const float* __restrict__ W_P,
                             const int*   __restrict__ cls_idx)
{
    const int i = blockIdx.x;
    const int j = threadIdx.x;

    __shared__ float su[CLSD];          // relu(W_U[ci][k]) * W_P[k]
    __shared__ float wpos_s[4][POSD];
    __shared__ float wp2[POSD];

    const int ci = cls_idx[i] - 1;
    {
        const int k = j;
        su[k] = fmaxf(W_U[ci * CLSD + k], 0.0f) * W_P[k];
        if (k < POSD) {
            wp2[k]       = W_P[CLSD + k];
            wpos_s[0][k] = W_pos[0 * POSD + k];
            wpos_s[1][k] = W_pos[1 * POSD + k];
            wpos_s[2][k] = W_pos[2 * POSD + k];
            wpos_s[3][k] = W_pos[3 * POSD + k];
        }
    }
    __syncthreads();

    const int cj = cls_idx[j] - 1;
    const float* __restrict__ wv = W_V + cj * CLSD;

    float acc = 0.0f;
#pragma unroll 8
    for (int k = 0; k < CLSD; k++)
        acc += su[k] * fmaxf(__ldg(&wv[k]), 0.0f);

    // position features
    const float xi0 = bbox[i*4+0], yi0 = bbox[i*4+1], xi1 = bbox[i*4+2], yi1 = bbox[i*4+3];
    const float xj0 = bbox[j*4+0], yj0 = bbox[j*4+1], xj1 = bbox[j*4+2], yj1 = bbox[j*4+3];
    const float wi = xi1 - xi0, hi = yi1 - yi0;
    const float wj = xj1 - xj0, hj = yj1 - yj0;
    const float xci = 0.5f*(xi0+xi1), yci = 0.5f*(yi0+yi1);
    const float xcj = 0.5f*(xj0+xj1), ycj = 0.5f*(yj0+yj1);

    const float dx = __fdividef(xcj - xci, wi);   // -(xc_i - xc_j)/w_i
    const float dy = __fdividef(ycj - yci, hi);
    const float dw = __logf(__fdividef(wj, wi));
    const float dh = __logf(__fdividef(hj, hi));

#pragma unroll 8
    for (int d = 0; d < POSD; d++) {
        float t = dx * wpos_s[0][d] + dy * wpos_s[1][d]
                + dw * wpos_s[2][d] + dh * wpos_s[3][d];
        acc += fmaxf(t, 0.0f) * wp2[d];
    }

    g_S[i * N_OBJ + j] = fsigmoid(acc);
}

// ---------------------------------------------------------------------------
// Kernel B: relT[m][n] = relu(S[n][m] - S[m][n])   (transposed for kernel C)
// ---------------------------------------------------------------------------
__global__ void rel_kernel()
{
    const int m = blockIdx.x;
    const int n = threadIdx.x;
    const float s_nm = g_S[n * N_OBJ + m];
    const float s_mn = g_S[m * N_OBJ + n];
    g_relT[m * N_OBJ + n] = fmaxf(s_nm - s_mn, 0.0f);
}

// ---------------------------------------------------------------------------
// Kernel C: out[n,p] = L[n,p] * (1 - sigmoid(L[n,p]) * sum_m relT[m][n]*sigmoid(L[m,p]))
// grid: 288 blocks x 256 threads; block = 128 pixels x all 128 n
// packed fp32x2 FMA via PTX (FFMA2) for 2x math throughput
// ---------------------------------------------------------------------------
#define FMA2(d, a, b, c) \
    asm("fma.rn.f32x2 %0, %1, %2, %3;" : "=l"(d) : "l"(a), "l"(b), "l"(c))
#define PACK2(d, x) \
    asm("mov.b64 %0, {%1, %1};" : "=l"(d) : "r"(__float_as_uint(x)))

__global__ void __launch_bounds__(256, 2)
main_kernel(const float* __restrict__ L, float* __restrict__ out)
{
    __shared__ float rel_s [KC][N_OBJ];   // 16 KB : relT[m][n] chunk
    __shared__ float prob_s[KC][TP];      // 16 KB : sigmoid(L[m][p]) chunk

    const int tid = threadIdx.x;
    const int tx  = tid & 15;             // pixel group: pixels 8*tx .. 8*tx+7
    const int ty  = tid >> 4;             // n group:     n = 8*ty .. 8*ty+7
    const int pbase = blockIdx.x * TP;

    unsigned long long acc[8][4];
#pragma unroll
    for (int r = 0; r < 8; r++)
#pragma unroll
        for (int q = 0; q < 4; q++) acc[r][q] = 0ull;

    for (int c = 0; c < N_OBJ / KC; c++) {
        __syncthreads();
        // --- stage sigmoid(L) chunk: KC x TP = 4096 floats ---
#pragma unroll
        for (int e = 0; e < (KC * TP) / 256; e++) {
            int idx = tid + e * 256;
            int m = idx >> 7;             // TP == 128
            int p = idx & 127;
            float l = L[(size_t)(c * KC + m) * HW + pbase + p];
            prob_s[m][p] = fsigmoid(l);
        }
        // --- stage rel chunk: KC x 128 = 4096 floats (coalesced: relT is m-major) ---
#pragma unroll
        for (int e = 0; e < (KC * N_OBJ) / 256; e++) {
            int idx = tid + e * 256;
            int m = idx >> 7;
            int n = idx & 127;
            rel_s[m][n] = g_relT[(c * KC + m) * N_OBJ + n];
        }
        __syncthreads();

#pragma unroll 4
        for (int m = 0; m < KC; m++) {
            // 8 rel values for this thread's n-range (broadcast across tx)
            float4 ra = *(const float4*)&rel_s[m][ty * 8];
            float4 rb = *(const float4*)&rel_s[m][ty * 8 + 4];
            float rv[8] = {ra.x, ra.y, ra.z, ra.w, rb.x, rb.y, rb.z, rb.w};
            unsigned long long rp[8];
#pragma unroll
            for (int r = 0; r < 8; r++) PACK2(rp[r], rv[r]);

            // 8 prob values = 4 packed pairs for this thread's pixels
            ulonglong2 pa = *(const ulonglong2*)&prob_s[m][tx * 8];
            ulonglong2 pb = *(const ulonglong2*)&prob_s[m][tx * 8 + 4];
            unsigned long long pv[4] = {pa.x, pa.y, pb.x, pb.y};

#pragma unroll
            for (int r = 0; r < 8; r++) {
                FMA2(acc[r][0], rp[r], pv[0], acc[r][0]);
                FMA2(acc[r][1], rp[r], pv[1], acc[r][1]);
                FMA2(acc[r][2], rp[r], pv[2], acc[r][2]);
                FMA2(acc[r][3], rp[r], pv[3], acc[r][3]);
            }
        }
    }

    // --- epilogue: out = L * (1 - sigmoid(L) * weighted) ---
#pragma unroll
    for (int r = 0; r < 8; r++) {
        const int n = ty * 8 + r;
        const size_t off = (size_t)n * HW + pbase + tx * 8;
        float4 l0 = *(const float4*)&L[off];
        float4 l1 = *(const float4*)&L[off + 4];

        float w[8];
#pragma unroll
        for (int q = 0; q < 4; q++) {
            w[2*q]   = __uint_as_float((unsigned int)(acc[r][q] & 0xFFFFFFFFull));
            w[2*q+1] = __uint_as_float((unsigned int)(acc[r][q] >> 32));
        }

        float lv[8] = {l0.x, l0.y, l0.z, l0.w, l1.x, l1.y, l1.z, l1.w};
        float ov[8];
#pragma unroll
        for (int k = 0; k < 8; k++)
            ov[k] = lv[k] * (1.0f - fsigmoid(lv[k]) * w[k]);

        float4 o0 = {ov[0], ov[1], ov[2], ov[3]};
        float4 o1 = {ov[4], ov[5], ov[6], ov[7]};
        *(float4*)&out[off]     = o0;
        *(float4*)&out[off + 4] = o1;
    }
}

// ---------------------------------------------------------------------------
extern "C" void kernel_launch(void* const* d_in, const int* in_sizes, int n_in,
                              void* d_out, int out_size)
{
    const float* L     = (const float*)d_in[0];   // mask_logits (1,128,192,192)
    const float* bbox  = (const float*)d_in[1];   // (128,4)
    const float* W_U   = (const float*)d_in[2];   // (80,128)
    const float* W_V   = (const float*)d_in[3];   // (80,128)
    const float* W_pos = (const float*)d_in[4];   // (4,64)
    const float* W_P   = (const float*)d_in[5];   // (192,1)
    const int*   cls   = (const int*)d_in[6];     // (128,)
    float* out = (float*)d_out;

    score_kernel<<<N_OBJ, N_OBJ>>>(bbox, W_U, W_V, W_pos, W_P, cls);
    rel_kernel<<<N_OBJ, N_OBJ>>>();
    main_kernel<<<HW / TP, 256>>>(L, out);
}

// round 3
// speedup vs baseline: 1.6180x; 1.6180x over previous
#include <cuda_runtime.h>
#include <cuda_bf16.h>
#include <math.h>
#include <stdint.h>

#define N_OBJ   128
#define HW      36864      // 192*192
#define CLSD    128
#define POSD    64
#define NCLS    80         // THING-1
#define TP      128        // pixels per block tile
#define ROWB    272        // padded row stride in bytes (17 x 16B, ldmatrix-aligned)

// -------- scratch (__device__ globals; no allocations allowed) --------------
__device__ float         g_S[N_OBJ * N_OBJ];      // sigmoid overlap scores [i][j]
__device__ __nv_bfloat16 g_relh[N_OBJ * N_OBJ];   // relation hi, [n][m]
__device__ __nv_bfloat16 g_rell[N_OBJ * N_OBJ];   // relation lo, [n][m]

__device__ __forceinline__ float fsigmoid(float x) {
    return __fdividef(1.0f, 1.0f + __expf(-x));
}

__device__ __forceinline__ uint32_t smem_u32(const void* p) {
    uint32_t a;
    asm("{ .reg .u64 t; cvta.to.shared.u64 t, %1; cvt.u32.u64 %0, t; }" : "=r"(a) : "l"(p));
    return a;
}

// ldmatrix: 4x 8x8 b16 tiles (non-transposed)
__device__ __forceinline__ void ldmx4(uint32_t r[4], uint32_t addr) {
    asm volatile("ldmatrix.sync.aligned.m8n8.x4.shared.b16 {%0,%1,%2,%3}, [%4];"
        : "=r"(r[0]), "=r"(r[1]), "=r"(r[2]), "=r"(r[3]) : "r"(addr));
}
// ldmatrix: 2x 8x8 b16 tiles, transposed
__device__ __forceinline__ void ldmx2t(uint32_t r[2], uint32_t addr) {
    asm volatile("ldmatrix.sync.aligned.m8n8.x2.trans.shared.b16 {%0,%1}, [%2];"
        : "=r"(r[0]), "=r"(r[1]) : "r"(addr));
}
// D += A * B  (m16n8k16, bf16 in, f32 acc)
__device__ __forceinline__ void mma_bf16(float c[4], const uint32_t a[4], const uint32_t b[2]) {
    asm volatile(
        "mma.sync.aligned.m16n8k16.row.col.f32.bf16.bf16.f32 "
        "{%0,%1,%2,%3}, {%4,%5,%6,%7}, {%8,%9}, {%0,%1,%2,%3};"
        : "+f"(c[0]), "+f"(c[1]), "+f"(c[2]), "+f"(c[3])
        : "r"(a[0]), "r"(a[1]), "r"(a[2]), "r"(a[3]), "r"(b[0]), "r"(b[1]));
}

// ============================================================================
// Kernel A: S[i][j] = sigmoid(cls_term + pos_term); relu(W_V)^T staged in smem
// ============================================================================
__global__ void score_kernel(const float* __restrict__ bbox,
                             const float* __restrict__ W_U,
                             const float* __restrict__ W_V,
                             const float* __restrict__ W_pos,
                             const float* __restrict__ W_P,
                             const int*   __restrict__ cls_idx)
{
    const int i = blockIdx.x;
    const int j = threadIdx.x;

    __shared__ float sVt[CLSD * 81];     // relu(W_V)^T : [k][c], pad 81
    __shared__ float su[CLSD];
    __shared__ float wpos_s[4][POSD];
    __shared__ float wp2[POSD];

    const int ci = cls_idx[i] - 1;
    su[j] = fmaxf(W_U[ci * CLSD + j], 0.0f) * W_P[j];
    if (j < POSD) {
        wp2[j]       = W_P[CLSD + j];
        wpos_s[0][j] = W_pos[0 * POSD + j];
        wpos_s[1][j] = W_pos[1 * POSD + j];
        wpos_s[2][j] = W_pos[2 * POSD + j];
        wpos_s[3][j] = W_pos[3 * POSD + j];
    }
#pragma unroll
    for (int c = 0; c < NCLS; c++)
        sVt[j * 81 + c] = fmaxf(W_V[c * CLSD + j], 0.0f);   // coalesced over j
    __syncthreads();

    const int cj = cls_idx[j] - 1;
    float acc = 0.0f;
#pragma unroll 8
    for (int k = 0; k < CLSD; k++)
        acc += su[k] * sVt[k * 81 + cj];

    const float xi0 = bbox[i*4+0], yi0 = bbox[i*4+1], xi1 = bbox[i*4+2], yi1 = bbox[i*4+3];
    const float xj0 = bbox[j*4+0], yj0 = bbox[j*4+1], xj1 = bbox[j*4+2], yj1 = bbox[j*4+3];
    const float wi = xi1 - xi0, hi = yi1 - yi0;
    const float wj = xj1 - xj0, hj = yj1 - yj0;
    const float dx = __fdividef(0.5f*(xj0+xj1) - 0.5f*(xi0+xi1), wi);
    const float dy = __fdividef(0.5f*(yj0+yj1) - 0.5f*(yi0+yi1), hi);
    const float dw = __logf(__fdividef(wj, wi));
    const float dh = __logf(__fdividef(hj, hi));

#pragma unroll 8
    for (int d = 0; d < POSD; d++) {
        float t = dx * wpos_s[0][d] + dy * wpos_s[1][d]
                + dw * wpos_s[2][d] + dh * wpos_s[3][d];
        acc += fmaxf(t, 0.0f) * wp2[d];
    }

    g_S[i * N_OBJ + j] = fsigmoid(acc);
}

// ============================================================================
// Kernel B: rel[n][m] = relu(S[n][m]-S[m][n]) split into bf16 hi+lo
// ============================================================================
__global__ void rel_kernel()
{
    const int n = blockIdx.x;
    const int m = threadIdx.x;
    const float r = fmaxf(g_S[n * N_OBJ + m] - g_S[m * N_OBJ + n], 0.0f);
    __nv_bfloat16 h = __float2bfloat16(r);
    __nv_bfloat16 l = __float2bfloat16(r - __bfloat162float(h));
    g_relh[n * N_OBJ + m] = h;
    g_rell[n * N_OBJ + m] = l;
}

// ============================================================================
// Kernel C: 128-pixel tile GEMM via warp mma.sync (bf16 hi/lo, 3 passes),
//           fused epilogue out = L * (1 - sigmoid(L) * w)
// smem: A_hi | A_lo : rel [n][m], rows 128, stride 272B
//       B_hi | B_lo : sigmoid(L) [m][p], rows 128, stride 272B (trans-ldmatrix)
// ============================================================================
#define TILE_BYTES (128 * ROWB)      // 34816

__global__ void __launch_bounds__(256, 1)
main_kernel(const float* __restrict__ L, float* __restrict__ out)
{
    extern __shared__ __align__(128) char sm[];
    char* smAh = sm;
    char* smAl = sm + TILE_BYTES;
    char* smBh = sm + 2 * TILE_BYTES;
    char* smBl = sm + 3 * TILE_BYTES;

    const int tid  = threadIdx.x;
    const int wid  = tid >> 5;
    const int lane = tid & 31;
    const int P    = blockIdx.x * TP;

    // ---- stage A (rel hi/lo): contiguous u32 copies, conflict-free --------
    {
        const uint32_t* __restrict__ rh = (const uint32_t*)g_relh;
        const uint32_t* __restrict__ rl = (const uint32_t*)g_rell;
#pragma unroll
        for (int e = 0; e < 8192 / 256; e++) {
            int idx = tid + e * 256;
            int n = idx >> 6;               // row
            int mp = idx & 63;              // u32 (m-pair) index
            *(uint32_t*)(smAh + n * ROWB + mp * 4) = rh[idx];
            *(uint32_t*)(smAl + n * ROWB + mp * 4) = rl[idx];
        }
    }
    // ---- stage B (sigmoid(L) hi/lo, natural [m][p] orientation) -----------
#pragma unroll
    for (int e = 0; e < 16384 / 256; e++) {
        int idx = tid + e * 256;
        int m = idx >> 7;
        int p = idx & 127;                  // warp: p consecutive -> coalesced
        float s = fsigmoid(L[(size_t)m * HW + P + p]);
        __nv_bfloat16 h = __float2bfloat16(s);
        __nv_bfloat16 l = __float2bfloat16(s - __bfloat162float(h));
        *(__nv_bfloat16*)(smBh + m * ROWB + p * 2) = h;
        *(__nv_bfloat16*)(smBl + m * ROWB + p * 2) = l;
    }
    __syncthreads();

    // ---- warp tiling: 2 n-groups x 4 p-groups; each warp n64 x p32 --------
    const int nb = (wid >> 2) * 64;
    const int pb = (wid & 3) * 32;

    float acc[4][4][4];
#pragma unroll
    for (int a = 0; a < 4; a++)
#pragma unroll
        for (int b = 0; b < 4; b++)
#pragma unroll
            for (int q = 0; q < 4; q++) acc[a][b][q] = 0.0f;

    // lane addressing for ldmatrix
    const int a_grp = lane >> 3;
    const int a_row = (a_grp & 1) * 8 + (lane & 7);   // + nb + a*16
    const int a_col = (a_grp >> 1) * 8;               // + k0
    const int b_row = lane & 15;                      // + k0 (m row)

    const uint32_t uAh = smem_u32(smAh), uAl = smem_u32(smAl);
    const uint32_t uBh = smem_u32(smBh), uBl = smem_u32(smBl);

#pragma unroll
    for (int kc = 0; kc < 8; kc++) {
        const int k0 = kc * 16;

        uint32_t Ah[4][4], Al[4][4];
#pragma unroll
        for (int a = 0; a < 4; a++) {
            uint32_t off = (uint32_t)((nb + a * 16 + a_row) * ROWB + (k0 + a_col) * 2);
            ldmx4(Ah[a], uAh + off);
            ldmx4(Al[a], uAl + off);
        }
        uint32_t Bh[4][2], Bl[4][2];
#pragma unroll
        for (int b = 0; b < 4; b++) {
            uint32_t off = (uint32_t)((k0 + b_row) * ROWB + (pb + b * 8) * 2);
            ldmx2t(Bh[b], uBh + off);
            ldmx2t(Bl[b], uBl + off);
        }
#pragma unroll
        for (int a = 0; a < 4; a++)
#pragma unroll
            for (int b = 0; b < 4; b++) {
                mma_bf16(acc[a][b], Ah[a], Bh[b]);
                mma_bf16(acc[a][b], Ah[a], Bl[b]);
                mma_bf16(acc[a][b], Al[a], Bh[b]);
            }
    }

    // ---- epilogue straight from fragments: out = L*(1 - sigmoid(L)*w) -----
    const int g = lane >> 2, t = lane & 3;
#pragma unroll
    for (int a = 0; a < 4; a++) {
#pragma unroll
        for (int b = 0; b < 4; b++) {
            const int n0 = nb + a * 16 + g;
            const int p0 = P + pb + b * 8 + 2 * t;
            // c0:(n0,p0) c1:(n0,p0+1) c2:(n0+8,p0) c3:(n0+8,p0+1)
            {
                size_t off = (size_t)n0 * HW + p0;
                float2 lv = *(const float2*)&L[off];
                float2 ov;
                ov.x = lv.x * (1.0f - fsigmoid(lv.x) * acc[a][b][0]);
                ov.y = lv.y * (1.0f - fsigmoid(lv.y) * acc[a][b][1]);
                *(float2*)&out[off] = ov;
            }
            {
                size_t off = (size_t)(n0 + 8) * HW + p0;
                float2 lv = *(const float2*)&L[off];
                float2 ov;
                ov.x = lv.x * (1.0f - fsigmoid(lv.x) * acc[a][b][2]);
                ov.y = lv.y * (1.0f - fsigmoid(lv.y) * acc[a][b][3]);
                *(float2*)&out[off] = ov;
            }
        }
    }
}

// ============================================================================
extern "C" void kernel_launch(void* const* d_in, const int* in_sizes, int n_in,
                              void* d_out, int out_size)
{
    const float* L     = (const float*)d_in[0];   // mask_logits (1,128,192,192)
    const float* bbox  = (const float*)d_in[1];   // (128,4)
    const float* W_U   = (const float*)d_in[2];   // (80,128)
    const float* W_V   = (const float*)d_in[3];   // (80,128)
    const float* W_pos = (const float*)d_in[4];   // (4,64)
    const float* W_P   = (const float*)d_in[5];   // (192,1)
    const int*   cls   = (const int*)d_in[6];     // (128,)
    float* out = (float*)d_out;

    const int dyn_smem = 4 * TILE_BYTES;          // 139264 B
    cudaFuncSetAttribute(main_kernel,
                         cudaFuncAttributeMaxDynamicSharedMemorySize, dyn_smem);

    score_kernel<<<N_OBJ, N_OBJ>>>(bbox, W_U, W_V, W_pos, W_P, cls);
    rel_kernel<<<N_OBJ, N_OBJ>>>();
    main_kernel<<<HW / TP, 256, dyn_smem>>>(L, out);
}

// round 4
// speedup vs baseline: 2.2504x; 1.3908x over previous
#include <cuda_runtime.h>
#include <cuda_fp16.h>
#include <math.h>
#include <stdint.h>

#define N_OBJ   128
#define HW      36864      // 192*192
#define CLSD    128
#define POSD    64
#define TP      256        // pixels per block tile
#define ROWA    272        // A row stride bytes (17 x 16B, odd chunks -> LDSM conflict-free)
#define ROWB    528        // B row stride bytes (33 x 16B)

// -------- scratch (__device__ globals) --------------------------------------
__device__ float  g_S[N_OBJ * N_OBJ];      // sigmoid overlap scores [i][j]
__device__ __half g_rel[N_OBJ * N_OBJ];    // relation_score fp16, [n][m]

__device__ __forceinline__ float fsig(float x) {   // sigmoid via single MUFU
    float t;
    asm("tanh.approx.f32 %0, %1;" : "=f"(t) : "f"(0.5f * x));
    return fmaf(0.5f, t, 0.5f);
}

__device__ __forceinline__ uint32_t smem_u32(const void* p) {
    uint32_t a;
    asm("{ .reg .u64 t; cvta.to.shared.u64 t, %1; cvt.u32.u64 %0, t; }" : "=r"(a) : "l"(p));
    return a;
}
__device__ __forceinline__ void ldmx4(uint32_t r[4], uint32_t addr) {
    asm volatile("ldmatrix.sync.aligned.m8n8.x4.shared.b16 {%0,%1,%2,%3}, [%4];"
        : "=r"(r[0]), "=r"(r[1]), "=r"(r[2]), "=r"(r[3]) : "r"(addr));
}
__device__ __forceinline__ void ldmx2t(uint32_t r[2], uint32_t addr) {
    asm volatile("ldmatrix.sync.aligned.m8n8.x2.trans.shared.b16 {%0,%1}, [%2];"
        : "=r"(r[0]), "=r"(r[1]) : "r"(addr));
}
__device__ __forceinline__ void mma_fp16(float c[4], const uint32_t a[4], const uint32_t b[2]) {
    asm volatile(
        "mma.sync.aligned.m16n8k16.row.col.f32.f16.f16.f32 "
        "{%0,%1,%2,%3}, {%4,%5,%6,%7}, {%8,%9}, {%0,%1,%2,%3};"
        : "+f"(c[0]), "+f"(c[1]), "+f"(c[2]), "+f"(c[3])
        : "r"(a[0]), "r"(a[1]), "r"(a[2]), "r"(a[3]), "r"(b[0]), "r"(b[1]));
}

// ============================================================================
// Kernel A (score): warp-dot layout. Block = i, 8 warps x 16 j each.
// Lanes traverse k (coalesced LDG of gathered W_V rows) + shuffle reduce.
// ============================================================================
__global__ void __launch_bounds__(256)
score_kernel(const float* __restrict__ bbox,
             const float* __restrict__ W_U,
             const float* __restrict__ W_V,
             const float* __restrict__ W_pos,
             const float* __restrict__ W_P,
             const int*   __restrict__ cls_idx)
{
    const int i    = blockIdx.x;
    const int tid  = threadIdx.x;
    const int wid  = tid >> 5;
    const int lane = tid & 31;

    __shared__ float su[CLSD];               // relu(W_U[ci,k]) * W_P[k]
    __shared__ float wpos_s[4][POSD];
    __shared__ float wp2[POSD];
    __shared__ float gxc[N_OBJ], gyc[N_OBJ], gw[N_OBJ], gh[N_OBJ], glw[N_OBJ], glh[N_OBJ];
    __shared__ int   scls[N_OBJ];

    const int ci = cls_idx[i] - 1;
    if (tid < 128) {
        const int j = tid;
        su[j] = fmaxf(W_U[ci * CLSD + j], 0.0f) * W_P[j];
        float4 bb = *(const float4*)&bbox[j * 4];
        float w = bb.z - bb.x, h = bb.w - bb.y;
        gxc[j] = 0.5f * (bb.x + bb.z);
        gyc[j] = 0.5f * (bb.y + bb.w);
        gw[j]  = w;  gh[j] = h;
        glw[j] = __logf(w);  glh[j] = __logf(h);
        scls[j] = cls_idx[j] - 1;
    } else if (tid < 192) {
        const int d = tid - 128;
        wp2[d] = W_P[CLSD + d];
        wpos_s[0][d] = W_pos[0 * POSD + d];
        wpos_s[1][d] = W_pos[1 * POSD + d];
        wpos_s[2][d] = W_pos[2 * POSD + d];
        wpos_s[3][d] = W_pos[3 * POSD + d];
    }
    __syncthreads();

    const float rwi = __fdividef(1.0f, gw[i]);
    const float rhi = __fdividef(1.0f, gh[i]);
    const float xci = gxc[i], yci = gyc[i], lwi = glw[i], lhi = glh[i];
    const float4 uk = *(const float4*)&su[lane * 4];
    const float w0a = wpos_s[0][lane], w1a = wpos_s[1][lane],
                w2a = wpos_s[2][lane], w3a = wpos_s[3][lane], wpa = wp2[lane];
    const float w0b = wpos_s[0][lane + 32], w1b = wpos_s[1][lane + 32],
                w2b = wpos_s[2][lane + 32], w3b = wpos_s[3][lane + 32], wpb = wp2[lane + 32];

#pragma unroll 4
    for (int jj = 0; jj < 16; jj++) {
        const int j = wid * 16 + jj;
        const int cj = scls[j];
        float4 v = *(const float4*)&W_V[cj * CLSD + lane * 4];

        float acc = fmaxf(v.x, 0.0f) * uk.x + fmaxf(v.y, 0.0f) * uk.y
                  + fmaxf(v.z, 0.0f) * uk.z + fmaxf(v.w, 0.0f) * uk.w;

        const float dx = (gxc[j] - xci) * rwi;
        const float dy = (gyc[j] - yci) * rhi;
        const float dw = glw[j] - lwi;
        const float dh = glh[j] - lhi;

        float t1 = dx * w0a + dy * w1a + dw * w2a + dh * w3a;
        float t2 = dx * w0b + dy * w1b + dw * w2b + dh * w3b;
        acc += fmaxf(t1, 0.0f) * wpa + fmaxf(t2, 0.0f) * wpb;

#pragma unroll
        for (int o = 16; o > 0; o >>= 1)
            acc += __shfl_xor_sync(0xFFFFFFFFu, acc, o);

        if (lane == 0) g_S[i * N_OBJ + j] = fsig(acc);
    }
}

// ============================================================================
// Kernel B: rel[n][m] = relu(S[n][m]-S[m][n]) -> fp16
// ============================================================================
__global__ void rel_kernel()
{
    const int n = blockIdx.x;
    const int m = threadIdx.x;
    const float r = fmaxf(g_S[n * N_OBJ + m] - g_S[m * N_OBJ + n], 0.0f);
    g_rel[n * N_OBJ + m] = __float2half_rn(r);
}

// ============================================================================
// Kernel C: 256-pixel tile, single-pass fp16 mma.sync GEMM + fused epilogue
// smem: A : rel [n][m] fp16, 128 rows x 272B  (34816 B)
//       B : sigmoid(L) [m][p] fp16, 128 rows x 528B (67584 B)
// ============================================================================
#define A_BYTES (128 * ROWA)
#define B_BYTES (128 * ROWB)

__global__ void __launch_bounds__(256, 1)
main_kernel(const float* __restrict__ L, float* __restrict__ out)
{
    extern __shared__ __align__(128) char sm[];
    char* smA = sm;
    char* smB = sm + A_BYTES;

    const int tid  = threadIdx.x;
    const int wid  = tid >> 5;
    const int lane = tid & 31;
    const int P    = blockIdx.x * TP;

    // ---- stage A (rel fp16): contiguous u32 copies -------------------------
    {
        const uint32_t* __restrict__ rr = (const uint32_t*)g_rel;
#pragma unroll
        for (int e = 0; e < 8192 / 256; e++) {
            int idx = tid + e * 256;
            int n = idx >> 6, mp = idx & 63;
            *(uint32_t*)(smA + n * ROWA + mp * 4) = rr[idx];
        }
    }
    // ---- stage B: sigmoid(L) -> fp16, natural [m][p], half2 stores --------
#pragma unroll
    for (int e = 0; e < 16384 / 256; e++) {
        int idx = tid + e * 256;          // half2 index
        int m = idx >> 7, pp = idx & 127;
        float2 l2 = *(const float2*)&L[(size_t)m * HW + P + pp * 2];
        __half2 h2 = __floats2half2_rn(fsig(l2.x), fsig(l2.y));
        *(__half2*)(smB + m * ROWB + pp * 4) = h2;
    }
    __syncthreads();

    // ---- warp tiling: 2 n-groups x 4 p-groups; warp = n64 x p64 ------------
    const int nb = (wid >> 2) * 64;
    const int pb = (wid & 3) * 64;

    float acc[4][8][4];
#pragma unroll
    for (int a = 0; a < 4; a++)
#pragma unroll
        for (int b = 0; b < 8; b++)
#pragma unroll
            for (int q = 0; q < 4; q++) acc[a][b][q] = 0.0f;

    const int a_grp = lane >> 3;
    const int a_row = (a_grp & 1) * 8 + (lane & 7);
    const int a_col = (a_grp >> 1) * 8;
    const int b_row = lane & 15;

    const uint32_t uA = smem_u32(smA);
    const uint32_t uB = smem_u32(smB);

#pragma unroll
    for (int kc = 0; kc < 8; kc++) {
        const int k0 = kc * 16;

        uint32_t Af[4][4];
#pragma unroll
        for (int a = 0; a < 4; a++)
            ldmx4(Af[a], uA + (uint32_t)((nb + a * 16 + a_row) * ROWA + (k0 + a_col) * 2));

        uint32_t Bf[8][2];
#pragma unroll
        for (int b = 0; b < 8; b++)
            ldmx2t(Bf[b], uB + (uint32_t)((k0 + b_row) * ROWB + (pb + b * 8) * 2));

#pragma unroll
        for (int a = 0; a < 4; a++)
#pragma unroll
            for (int b = 0; b < 8; b++)
                mma_fp16(acc[a][b], Af[a], Bf[b]);
    }

    // ---- epilogue from fragments: out = L*(1 - sigmoid(L)*w) ---------------
    const int g = lane >> 2, t = lane & 3;
#pragma unroll
    for (int a = 0; a < 4; a++) {
#pragma unroll
        for (int b = 0; b < 8; b++) {
            const int n0 = nb + a * 16 + g;
            const int p0 = P + pb + b * 8 + 2 * t;
            {
                size_t off = (size_t)n0 * HW + p0;
                float2 lv = *(const float2*)&L[off];
                float2 ov;
                ov.x = lv.x * (1.0f - fsig(lv.x) * acc[a][b][0]);
                ov.y = lv.y * (1.0f - fsig(lv.y) * acc[a][b][1]);
                *(float2*)&out[off] = ov;
            }
            {
                size_t off = (size_t)(n0 + 8) * HW + p0;
                float2 lv = *(const float2*)&L[off];
                float2 ov;
                ov.x = lv.x * (1.0f - fsig(lv.x) * acc[a][b][2]);
                ov.y = lv.y * (1.0f - fsig(lv.y) * acc[a][b][3]);
                *(float2*)&out[off] = ov;
            }
        }
    }
}

// ============================================================================
extern "C" void kernel_launch(void* const* d_in, const int* in_sizes, int n_in,
                              void* d_out, int out_size)
{
    const float* L     = (const float*)d_in[0];   // mask_logits (1,128,192,192)
    const float* bbox  = (const float*)d_in[1];   // (128,4)
    const float* W_U   = (const float*)d_in[2];   // (80,128)
    const float* W_V   = (const float*)d_in[3];   // (80,128)
    const float* W_pos = (const float*)d_in[4];   // (4,64)
    const float* W_P   = (const float*)d_in[5];   // (192,1)
    const int*   cls   = (const int*)d_in[6];     // (128,)
    float* out = (float*)d_out;

    const int dyn_smem = A_BYTES + B_BYTES;       // 102400 B
    cudaFuncSetAttribute(main_kernel,
                         cudaFuncAttributeMaxDynamicSharedMemorySize, dyn_smem);

    score_kernel<<<N_OBJ, 256>>>(bbox, W_U, W_V, W_pos, W_P, cls);
    rel_kernel<<<N_OBJ, N_OBJ>>>();
    main_kernel<<<HW / TP, 256, dyn_smem>>>(L, out);
}